// round 8
// baseline (speedup 1.0000x reference)
#include <cuda_runtime.h>
#include <cuda_bf16.h>
#include <cstdint>

// Problem constants
#define B    4
#define C    96
#define C3   288
#define HH   256
#define WW   256
#define HWPIX 65536
#define HEADS 3
#define HC   32
#define OUT_ELEMS (B * C * HWPIX)

// ---------------- scratch (device globals) ----------------
__device__ float g_qkv[(size_t)B * C3 * HWPIX];  // post 1x1 conv (fp32)
__device__ float g_v  [(size_t)B * C  * HWPIX];  // post dw, v only, packed {bf16 hi, bf16 lo}
__device__ float g_G  [B * HEADS * HC * HC];
__device__ float g_qn [B * C];
__device__ float g_kn [B * C];
__device__ float g_M  [B * C * C];

// ---------------- helpers ----------------
__device__ __forceinline__ uint32_t packbf(float lo, float hi) {
    uint32_t r;
    asm("cvt.rn.bf16x2.f32 %0, %1, %2;" : "=r"(r) : "f"(hi), "f"(lo));
    return r;
}
__device__ __forceinline__ uint16_t bf16bits(float v) {
    __nv_bfloat16 h = __float2bfloat16(v);
    __nv_bfloat16_raw raw = h;
    return raw.x;
}
__device__ __forceinline__ float bf16val(float v) {
    return __bfloat162float(__float2bfloat16(v));
}
__device__ __forceinline__ uint32_t prmt0(uint32_t a, uint32_t sel) {
    uint32_t d, z = 0;
    asm("prmt.b32 %0, %1, %2, %3;" : "=r"(d) : "r"(a), "r"(z), "r"(sel));
    return d;
}
__device__ __forceinline__ uint32_t prmt2(uint32_t a, uint32_t b, uint32_t sel) {
    uint32_t d;
    asm("prmt.b32 %0, %1, %2, %3;" : "=r"(d) : "r"(a), "r"(b), "r"(sel));
    return d;
}

__device__ __forceinline__ void mma16816(float c[4], const uint32_t a[4],
                                         const uint32_t b[2]) {
    asm volatile(
        "mma.sync.aligned.m16n8k16.row.col.f32.bf16.bf16.f32 "
        "{%0,%1,%2,%3}, {%4,%5,%6,%7}, {%8,%9}, {%0,%1,%2,%3};"
        : "+f"(c[0]), "+f"(c[1]), "+f"(c[2]), "+f"(c[3])
        : "r"(a[0]), "r"(a[1]), "r"(a[2]), "r"(a[3]), "r"(b[0]), "r"(b[1]));
}

// ================= tensor-core GEMM via mma.sync (bf16 hi/lo 3-product) ====
#define KP 104  // bf16 pitch

template<int NG>
__global__ __launch_bounds__(256) void tmma_gemm(
    const float* __restrict__ Xin, const float* __restrict__ Win,
    const float* __restrict__ bias, float* __restrict__ Oout)
{
    extern __shared__ __align__(16) uint16_t sm[];
    uint16_t* sbh = sm;                       // B hi [128][KP]
    uint16_t* sbl = sm + 128 * KP;            // B lo
    uint16_t* sah = sm + 2 * 128 * KP;        // A hi [96][KP]
    uint16_t* sal = sm + 2 * 128 * KP + 96 * KP;

    const int tid  = threadIdx.x;
    const int warp = tid >> 5;
    const int l    = tid & 31;
    const int b    = blockIdx.z;
    const long n0  = (long)blockIdx.x * 128;

    const float* Xb; const float* Wb; float* Ob;
    if constexpr (NG == 3) {
        Xb = Xin + (long)b * C * HWPIX;
        Wb = Win;
        Ob = g_qkv + (long)b * C3 * HWPIX;
    } else {
        Xb = g_v + (long)b * C * HWPIX;             // v channels (packed uint32)
        Wb = g_M + (long)b * C * C;
        Ob = Oout + (long)b * C * HWPIX;
    }

    // ---- B tile: X[k][px] -> smem [px][k] bf16 hi/lo ----
    {
        const int px = tid & 127;
        const int kh = tid >> 7;
        if constexpr (NG == 3) {
            for (int k2 = kh; k2 < 48; k2 += 2) {
                const int k = k2 * 2;
                float v0 = Xb[(long)k * HWPIX + n0 + px];
                float v1 = Xb[(long)(k + 1) * HWPIX + n0 + px];
                float h0 = bf16val(v0);
                float h1 = bf16val(v1);
                *(uint32_t*)&sbh[px * KP + k] = packbf(v0, v1);
                *(uint32_t*)&sbl[px * KP + k] = packbf(v0 - h0, v1 - h1);
            }
        } else {
            const uint32_t* Xp = (const uint32_t*)Xb;
            for (int k2 = kh; k2 < 48; k2 += 2) {
                const int k = k2 * 2;
                uint32_t w0 = Xp[(long)k * HWPIX + n0 + px];
                uint32_t w1 = Xp[(long)(k + 1) * HWPIX + n0 + px];
                *(uint32_t*)&sbh[px * KP + k] = prmt2(w0, w1, 0x5410u);
                *(uint32_t*)&sbl[px * KP + k] = prmt2(w0, w1, 0x7632u);
            }
        }
    }

    const int wpx = warp * 16;
    const int lr = l >> 2;
    const int lc = (l & 3) * 2;

    for (int g = 0; g < NG; g++) {
        __syncthreads();
        const float* Wg = Wb + (long)g * 96 * 96;
        for (int i = tid; i < 96 * 96; i += 256) {
            int m = i / 96, k = i - m * 96;
            float w = Wg[i];
            sah[m * KP + k] = bf16bits(w);
            sal[m * KP + k] = bf16bits(w - bf16val(w));
        }
        __syncthreads();

        float c[6][2][4];
#pragma unroll
        for (int mt = 0; mt < 6; mt++)
#pragma unroll
            for (int nt = 0; nt < 2; nt++)
#pragma unroll
                for (int j = 0; j < 4; j++) c[mt][nt][j] = 0.f;

#pragma unroll
        for (int s = 0; s < 6; s++) {
            const int k0 = s * 16;
            uint32_t bh[2][2], bl[2][2];
#pragma unroll
            for (int nt = 0; nt < 2; nt++) {
                const int n = wpx + nt * 8 + lr;
                bh[nt][0] = *(const uint32_t*)&sbh[n * KP + k0 + lc];
                bh[nt][1] = *(const uint32_t*)&sbh[n * KP + k0 + lc + 8];
                bl[nt][0] = *(const uint32_t*)&sbl[n * KP + k0 + lc];
                bl[nt][1] = *(const uint32_t*)&sbl[n * KP + k0 + lc + 8];
            }
#pragma unroll
            for (int mt = 0; mt < 6; mt++) {
                const int r = mt * 16 + lr;
                uint32_t ah[4], al[4];
                ah[0] = *(const uint32_t*)&sah[r * KP + k0 + lc];
                ah[1] = *(const uint32_t*)&sah[(r + 8) * KP + k0 + lc];
                ah[2] = *(const uint32_t*)&sah[r * KP + k0 + lc + 8];
                ah[3] = *(const uint32_t*)&sah[(r + 8) * KP + k0 + lc + 8];
                al[0] = *(const uint32_t*)&sal[r * KP + k0 + lc];
                al[1] = *(const uint32_t*)&sal[(r + 8) * KP + k0 + lc];
                al[2] = *(const uint32_t*)&sal[r * KP + k0 + lc + 8];
                al[3] = *(const uint32_t*)&sal[(r + 8) * KP + k0 + lc + 8];
#pragma unroll
                for (int nt = 0; nt < 2; nt++) {
                    mma16816(c[mt][nt], ah, bh[nt]);
                    mma16816(c[mt][nt], ah, bl[nt]);
                    mma16816(c[mt][nt], al, bh[nt]);
                }
            }
        }

#pragma unroll
        for (int mt = 0; mt < 6; mt++) {
#pragma unroll
            for (int nt = 0; nt < 2; nt++) {
                const int ch0 = g * 96 + mt * 16 + lr;
                const long px = n0 + wpx + nt * 8 + lc;
                float b0 = __ldg(&bias[ch0]);
                float b1 = __ldg(&bias[ch0 + 8]);
                float2 v0 = { c[mt][nt][0] + b0, c[mt][nt][1] + b0 };
                float2 v1 = { c[mt][nt][2] + b1, c[mt][nt][3] + b1 };
                *(float2*)&Ob[(long)ch0 * HWPIX + px] = v0;
                *(float2*)&Ob[(long)(ch0 + 8) * HWPIX + px] = v1;
            }
        }
    }
}

// ---------------- K0: zero small accumulators ----------------
__global__ void zero_small() {
    int i = blockIdx.x * blockDim.x + threadIdx.x;
    if (i < B * HEADS * HC * HC) g_G[i] = 0.f;
    if (i < B * C) { g_qn[i] = 0.f; g_kn[i] = 0.f; }
}

// ================= K2: FUSED dwconv(q,k) + norms + Gram (mma) ==============
// grid (128 tiles, 3 heads, 4 b), block 512 (16 warps).
// Tile = 8 rows x 64 cols = 512 px. q,k conv results live ONLY in smem.
// smem: qs[32][516] + ks[32][516] uint32 (132 KB); partials reuse qs.
#define DGP 516
__global__ __launch_bounds__(512) void dwgram(
    const float* __restrict__ dw_w, const float* __restrict__ dw_b)
{
    extern __shared__ uint32_t dsm[];
    uint32_t* qs = dsm;
    uint32_t* ks = dsm + 32 * DGP;
    float* red = (float*)dsm;            // [16][1024] reuse after phase B reads

    const int tid = threadIdx.x;
    const int h = blockIdx.y, b = blockIdx.z;
    const int y0 = (blockIdx.x >> 2) * 8;
    const int x0 = (blockIdx.x & 3) * 64;

    // ---- phase A: depthwise conv for 64 channels (2 units/thread, same ch) ----
    float ss = 0.f;
    int ssch = -1;
#pragma unroll
    for (int i = 0; i < 2; i++) {
        const int u = tid * 2 + i;           // 0..1023
        const int chl = u >> 4;              // 0..63 (both units same chl)
        const int colq = u & 15;
        const int ch = (chl < 32) ? (h * HC + chl) : (96 + h * HC + (chl - 32));
        ssch = chl;
        const float* P = g_qkv + ((long)(b * C3 + ch)) * HWPIX;
        uint32_t* dst = ((chl < 32) ? qs : ks) + (chl & 31) * DGP;

        float w[9];
#pragma unroll
        for (int t = 0; t < 9; t++) w[t] = __ldg(&dw_w[ch * 9 + t]);
        const float bias = __ldg(&dw_b[ch]);

        const int col0 = x0 + colq * 4;
        float A[6], Bw[6], Cw[6];
        auto loadrow = [&](int y, float* v) {
            if ((unsigned)y < 256u) {
                const float* row = P + y * WW + col0;
                float4 m = *(const float4*)row;
                v[0] = (col0 > 0)   ? __ldg(row - 1) : 0.f;
                v[1] = m.x; v[2] = m.y; v[3] = m.z; v[4] = m.w;
                v[5] = (col0 < 252) ? __ldg(row + 4) : 0.f;
            } else {
#pragma unroll
                for (int j = 0; j < 6; j++) v[j] = 0.f;
            }
        };
        loadrow(y0 - 1, A);
        loadrow(y0,     Bw);
#pragma unroll
        for (int dy = 0; dy < 8; dy++) {
            loadrow(y0 + dy + 1, Cw);
            uint32_t pk[4];
#pragma unroll
            for (int j = 0; j < 4; j++) {
                float o = bias
                    + w[0] * A[j]  + w[1] * A[j + 1]  + w[2] * A[j + 2]
                    + w[3] * Bw[j] + w[4] * Bw[j + 1] + w[5] * Bw[j + 2]
                    + w[6] * Cw[j] + w[7] * Cw[j + 1] + w[8] * Cw[j + 2];
                ss += o * o;
                pk[j] = packbf(o, o - bf16val(o));
            }
            *(uint4*)&dst[dy * 64 + colq * 4] = *(uint4*)pk;
#pragma unroll
            for (int j = 0; j < 6; j++) { A[j] = Bw[j]; Bw[j] = Cw[j]; }
        }
    }
    // norms: 8-lane groups share one channel
    ss += __shfl_down_sync(0xffffffffu, ss, 4);
    ss += __shfl_down_sync(0xffffffffu, ss, 2);
    ss += __shfl_down_sync(0xffffffffu, ss, 1);
    if ((tid & 7) == 0) {
        float* nd = (ssch < 32) ? &g_qn[b * C + h * HC + ssch]
                                : &g_kn[b * C + h * HC + (ssch - 32)];
        atomicAdd(nd, ss);
    }
    __syncthreads();

    // ---- phase B: Gram via mma (16 warps x 32 px) ----
    const int w16 = tid >> 5, l = tid & 31;
    const int lr = l >> 2, lq = l & 3;
    float c[2][4][4];
#pragma unroll
    for (int mt = 0; mt < 2; mt++)
#pragma unroll
        for (int nt = 0; nt < 4; nt++)
#pragma unroll
            for (int j = 0; j < 4; j++) c[mt][nt][j] = 0.f;

    const int pxw = w16 * 32;
#pragma unroll
    for (int st = 0; st < 4; st++) {
        const int pxb = pxw + st * 8;
        uint32_t bh[4][2], bl[4][2];
#pragma unroll
        for (int nt = 0; nt < 4; nt++) {
            uint32_t r0 = ks[(nt * 8 + lr) * DGP + pxb + lq];
            uint32_t r1 = ks[(nt * 8 + lr) * DGP + pxb + 4 + lq];
            bh[nt][0] = prmt0(r0, 0x1010u); bl[nt][0] = prmt0(r0, 0x4432u);
            bh[nt][1] = prmt0(r1, 0x1010u); bl[nt][1] = prmt0(r1, 0x4432u);
        }
#pragma unroll
        for (int mt = 0; mt < 2; mt++) {
            uint32_t a[4];
            a[0] = qs[(mt * 16 + lr) * DGP + pxb + lq];
            a[1] = qs[(mt * 16 + 8 + lr) * DGP + pxb + lq];
            a[2] = qs[(mt * 16 + lr) * DGP + pxb + 4 + lq];
            a[3] = qs[(mt * 16 + 8 + lr) * DGP + pxb + 4 + lq];
#pragma unroll
            for (int nt = 0; nt < 4; nt++) {
                mma16816(c[mt][nt], a, bh[nt]);
                mma16816(c[mt][nt], a, bl[nt]);
            }
        }
    }

    __syncthreads();   // all smem reads done before partial overwrite
#pragma unroll
    for (int mt = 0; mt < 2; mt++)
#pragma unroll
        for (int nt = 0; nt < 4; nt++)
#pragma unroll
            for (int j = 0; j < 4; j++) {
                int row = mt * 16 + lr + ((j >> 1) << 3);
                int cl  = nt * 8 + lq * 2 + (j & 1);
                red[w16 * 1024 + row * 32 + cl] = c[mt][nt][j];
            }
    __syncthreads();
    float* Gp = g_G + (long)(b * HEADS + h) * HC * HC;
    for (int i = tid; i < 1024; i += 512) {
        float sum = 0.f;
#pragma unroll
        for (int ww = 0; ww < 16; ww++) sum += red[ww * 1024 + i];
        atomicAdd(&Gp[i], sum);
    }
}

// ---------------- K2b: vectorized dwconv, v channels only ----------------
__global__ __launch_bounds__(256) void dwconv_v(
    const float* __restrict__ dw_w, const float* __restrict__ dw_b)
{
    const int tx = threadIdx.x, ty = threadIdx.y;
    const int vch = blockIdx.y;
    const int b  = blockIdx.z;
    const int ch = 192 + vch;
    const int col0 = tx * 4;
    const float* P = g_qkv + ((long)(b * C3 + ch)) * HWPIX;
    uint32_t*    O = (uint32_t*)(g_v + ((long)(b * C + vch)) * HWPIX);

    float w[9];
#pragma unroll
    for (int t = 0; t < 9; t++) w[t] = __ldg(&dw_w[ch * 9 + t]);
    const float bias = __ldg(&dw_b[ch]);

    const int y0 = blockIdx.x * 32 + ty * 8;
    float A[6], Bw[6], Cw[6];
    auto loadrow = [&](int y, float* v) {
        if ((unsigned)y < 256u) {
            const float* row = P + y * WW + col0;
            float4 m = *(const float4*)row;
            v[0] = (col0 > 0)   ? __ldg(row - 1) : 0.f;
            v[1] = m.x; v[2] = m.y; v[3] = m.z; v[4] = m.w;
            v[5] = (col0 < 252) ? __ldg(row + 4) : 0.f;
        } else {
#pragma unroll
            for (int j = 0; j < 6; j++) v[j] = 0.f;
        }
    };
    loadrow(y0 - 1, A);
    loadrow(y0,     Bw);
#pragma unroll
    for (int dy = 0; dy < 8; dy++) {
        loadrow(y0 + dy + 1, Cw);
        uint32_t pk[4];
#pragma unroll
        for (int j = 0; j < 4; j++) {
            float o = bias
                + w[0] * A[j]  + w[1] * A[j + 1]  + w[2] * A[j + 2]
                + w[3] * Bw[j] + w[4] * Bw[j + 1] + w[5] * Bw[j + 2]
                + w[6] * Cw[j] + w[7] * Cw[j + 1] + w[8] * Cw[j + 2];
            pk[j] = packbf(o, o - bf16val(o));
        }
        *(uint4*)&O[(y0 + dy) * WW + col0] = *(uint4*)pk;
#pragma unroll
        for (int j = 0; j < 6; j++) { A[j] = Bw[j]; Bw[j] = Cw[j]; }
    }
}

// ---------------- K3b: softmax(G / (||q|| ||k||)) -> d_out tail ------------
__global__ void attn_softmax(float* __restrict__ out)
{
    const int blk = blockIdx.x;
    const int b = blk / 3, h = blk % 3;
    const int c = threadIdx.x;
    float nq = fmaxf(sqrtf(g_qn[b * C + h * HC + c]), 1e-12f);

    float v[32];
#pragma unroll
    for (int d = 0; d < 32; d++) {
        float nk = fmaxf(sqrtf(g_kn[b * C + h * HC + d]), 1e-12f);
        v[d] = g_G[(blk * HC + c) * HC + d] / (nq * nk);
    }
    float m = -1e30f;
#pragma unroll
    for (int d = 0; d < 32; d++) m = fmaxf(m, v[d]);
    float s = 0.f;
#pragma unroll
    for (int d = 0; d < 32; d++) { v[d] = expf(v[d] - m); s += v[d]; }
    float inv = 1.f / s;
    float* ap = out + OUT_ELEMS + (long)blk * (HC * HC) + c * HC;
#pragma unroll
    for (int d = 0; d < 32; d++) ap[d] = v[d] * inv;
}

// ---------------- K3c: M[b] = proj_w @ blockdiag(attn[b]) ----------------
__global__ void make_M(const float* __restrict__ proj_w, const float* __restrict__ out)
{
    const int b = blockIdx.x, tid = threadIdx.x;
    const float* attn = out + OUT_ELEMS;
#pragma unroll 4
    for (int e = 0; e < 36; e++) {
        int idx = e * 256 + tid;
        int o = idx / 96, g = idx % 96;
        int h = g >> 5, d = g & 31;
        const float* arow = attn + (long)(b * HEADS + h) * (HC * HC) + d;
        const float* prow = proj_w + o * 96 + h * HC;
        float s = 0.f;
#pragma unroll
        for (int cc = 0; cc < 32; cc++) s += prow[cc] * arow[cc * 32];
        g_M[(long)b * C * C + idx] = s;
    }
}

// ---------------- launch ----------------
extern "C" void kernel_launch(void* const* d_in, const int* in_sizes, int n_in,
                              void* d_out, int out_size)
{
    const float* x      = (const float*)d_in[0];
    const float* qkv_w  = (const float*)d_in[1];
    const float* qkv_b  = (const float*)d_in[2];
    const float* dw_w   = (const float*)d_in[3];
    const float* dw_b   = (const float*)d_in[4];
    const float* proj_w = (const float*)d_in[5];
    const float* proj_b = (const float*)d_in[6];
    float* out = (float*)d_out;

    const int smem_gemm = (2 * 128 * KP + 2 * 96 * KP) * 2;   // 93,184 B
    const int smem_dwg  = 2 * 32 * DGP * 4;                   // 132,096 B
    cudaFuncSetAttribute(tmma_gemm<3>, cudaFuncAttributeMaxDynamicSharedMemorySize, smem_gemm);
    cudaFuncSetAttribute(tmma_gemm<1>, cudaFuncAttributeMaxDynamicSharedMemorySize, smem_gemm);
    cudaFuncSetAttribute(dwgram,       cudaFuncAttributeMaxDynamicSharedMemorySize, smem_dwg);

    zero_small<<<48, 256>>>();
    tmma_gemm<3><<<dim3(512, 1, B), 256, smem_gemm>>>(x, qkv_w, qkv_b, nullptr);
    dwgram<<<dim3(128, HEADS, B), 512, smem_dwg>>>(dw_w, dw_b);
    dwconv_v<<<dim3(8, 96, B), dim3(64, 4)>>>(dw_w, dw_b);
    attn_softmax<<<12, 32>>>(out);
    make_M<<<B, 256>>>(proj_w, out);
    tmma_gemm<1><<<dim3(512, 1, B), 256, smem_gemm>>>(nullptr, nullptr, proj_b, out);
}

// round 9
// speedup vs baseline: 1.1243x; 1.1243x over previous
#include <cuda_runtime.h>
#include <cuda_bf16.h>
#include <cuda_fp16.h>
#include <cstdint>

// Problem constants
#define B    4
#define C    96
#define C3   288
#define HH   256
#define WW   256
#define HWPIX 65536
#define HEADS 3
#define HC   32
#define OUT_ELEMS (B * C * HWPIX)

// ---------------- scratch (device globals) ----------------
__device__ float g_qkv[(size_t)B * C3 * HWPIX];  // post 1x1 conv (fp32)
__device__ float g_dw [(size_t)B * C3 * HWPIX];  // post dw; q,k packed bf16 hi/lo; v packed fp16 hi/lo
__device__ float g_G  [B * HEADS * HC * HC];
__device__ float g_qn [B * C];
__device__ float g_kn [B * C];
__device__ float g_M  [B * C * C];

// ---------------- helpers ----------------
__device__ __forceinline__ uint32_t packbf(float lo, float hi) {   // bf16x2
    uint32_t r;
    asm("cvt.rn.bf16x2.f32 %0, %1, %2;" : "=r"(r) : "f"(hi), "f"(lo));
    return r;
}
__device__ __forceinline__ uint32_t packh(float lo, float hi) {    // fp16x2
    uint32_t r;
    asm("cvt.rn.f16x2.f32 %0, %1, %2;" : "=r"(r) : "f"(hi), "f"(lo));
    return r;
}
__device__ __forceinline__ float bf16val(float v) {
    return __bfloat162float(__float2bfloat16(v));
}
__device__ __forceinline__ float h16val(float v) {
    return __half2float(__float2half_rn(v));
}
__device__ __forceinline__ uint16_t h16bits(float v) {
    __half h = __float2half_rn(v);
    __half_raw raw = h;
    return raw.x;
}
__device__ __forceinline__ uint32_t prmt0(uint32_t a, uint32_t sel) {
    uint32_t d, z = 0;
    asm("prmt.b32 %0, %1, %2, %3;" : "=r"(d) : "r"(a), "r"(z), "r"(sel));
    return d;
}
__device__ __forceinline__ uint32_t prmt2(uint32_t a, uint32_t b, uint32_t sel) {
    uint32_t d;
    asm("prmt.b32 %0, %1, %2, %3;" : "=r"(d) : "r"(a), "r"(b), "r"(sel));
    return d;
}

__device__ __forceinline__ void mma16816bf(float c[4], const uint32_t a[4],
                                           const uint32_t b[2]) {
    asm volatile(
        "mma.sync.aligned.m16n8k16.row.col.f32.bf16.bf16.f32 "
        "{%0,%1,%2,%3}, {%4,%5,%6,%7}, {%8,%9}, {%0,%1,%2,%3};"
        : "+f"(c[0]), "+f"(c[1]), "+f"(c[2]), "+f"(c[3])
        : "r"(a[0]), "r"(a[1]), "r"(a[2]), "r"(a[3]), "r"(b[0]), "r"(b[1]));
}
__device__ __forceinline__ void mma16816h(float c[4], const uint32_t a[4],
                                          const uint32_t b[2]) {
    asm volatile(
        "mma.sync.aligned.m16n8k16.row.col.f32.f16.f16.f32 "
        "{%0,%1,%2,%3}, {%4,%5,%6,%7}, {%8,%9}, {%0,%1,%2,%3};"
        : "+f"(c[0]), "+f"(c[1]), "+f"(c[2]), "+f"(c[3])
        : "r"(a[0]), "r"(a[1]), "r"(a[2]), "r"(a[3]), "r"(b[0]), "r"(b[1]));
}

// ========== tensor-core GEMM, fp16 2-product: A single fp16, B hi+lo fp16 ==
#define KP 104  // fp16 pitch

template<int NG>
__global__ __launch_bounds__(256) void tmma_gemm(
    const float* __restrict__ Xin, const float* __restrict__ Win,
    const float* __restrict__ bias, float* __restrict__ Oout)
{
    extern __shared__ __align__(16) uint16_t sm[];
    uint16_t* sbh = sm;                       // B hi [128][KP]
    uint16_t* sbl = sm + 128 * KP;            // B lo
    uint16_t* sah = sm + 2 * 128 * KP;        // A [96][KP] fp16

    const int tid  = threadIdx.x;
    const int warp = tid >> 5;
    const int l    = tid & 31;
    const int b    = blockIdx.z;
    const long n0  = (long)blockIdx.x * 128;

    const float* Xb; const float* Wb; float* Ob;
    if constexpr (NG == 3) {
        Xb = Xin + (long)b * C * HWPIX;
        Wb = Win;
        Ob = g_qkv + (long)b * C3 * HWPIX;
    } else {
        Xb = g_dw + ((long)b * C3 + 192) * HWPIX;   // v (packed fp16 hi/lo)
        Wb = g_M + (long)b * C * C;
        Ob = Oout + (long)b * C * HWPIX;
    }

    // ---- B tile: X[k][px] -> smem [px][k] fp16 hi/lo ----
    {
        const int px = tid & 127;
        const int kh = tid >> 7;
        if constexpr (NG == 3) {
            for (int k2 = kh; k2 < 48; k2 += 2) {
                const int k = k2 * 2;
                float v0 = Xb[(long)k * HWPIX + n0 + px];
                float v1 = Xb[(long)(k + 1) * HWPIX + n0 + px];
                float h0 = h16val(v0);
                float h1 = h16val(v1);
                *(uint32_t*)&sbh[px * KP + k] = packh(v0, v1);
                *(uint32_t*)&sbl[px * KP + k] = packh(v0 - h0, v1 - h1);
            }
        } else {
            const uint32_t* Xp = (const uint32_t*)Xb;
            for (int k2 = kh; k2 < 48; k2 += 2) {
                const int k = k2 * 2;
                uint32_t w0 = Xp[(long)k * HWPIX + n0 + px];
                uint32_t w1 = Xp[(long)(k + 1) * HWPIX + n0 + px];
                *(uint32_t*)&sbh[px * KP + k] = prmt2(w0, w1, 0x5410u);
                *(uint32_t*)&sbl[px * KP + k] = prmt2(w0, w1, 0x7632u);
            }
        }
    }

    const int wpx = warp * 16;
    const int lr = l >> 2;
    const int lc = (l & 3) * 2;

    for (int g = 0; g < NG; g++) {
        __syncthreads();
        // ---- A tile: W[g][m][k] -> smem fp16 (single plane) ----
        const float* Wg = Wb + (long)g * 96 * 96;
        for (int i = tid; i < 96 * 48; i += 256) {
            int m = i / 48, kp_ = (i - m * 48) * 2;
            float2 wv = *(const float2*)&Wg[m * 96 + kp_];
            *(uint32_t*)&sah[m * KP + kp_] = packh(wv.x, wv.y);
        }
        __syncthreads();

        float c[6][2][4];
#pragma unroll
        for (int mt = 0; mt < 6; mt++)
#pragma unroll
            for (int nt = 0; nt < 2; nt++)
#pragma unroll
                for (int j = 0; j < 4; j++) c[mt][nt][j] = 0.f;

#pragma unroll
        for (int s = 0; s < 6; s++) {
            const int k0 = s * 16;
            uint32_t bh[2][2], bl[2][2];
#pragma unroll
            for (int nt = 0; nt < 2; nt++) {
                const int n = wpx + nt * 8 + lr;
                bh[nt][0] = *(const uint32_t*)&sbh[n * KP + k0 + lc];
                bh[nt][1] = *(const uint32_t*)&sbh[n * KP + k0 + lc + 8];
                bl[nt][0] = *(const uint32_t*)&sbl[n * KP + k0 + lc];
                bl[nt][1] = *(const uint32_t*)&sbl[n * KP + k0 + lc + 8];
            }
#pragma unroll
            for (int mt = 0; mt < 6; mt++) {
                const int r = mt * 16 + lr;
                uint32_t ah[4];
                ah[0] = *(const uint32_t*)&sah[r * KP + k0 + lc];
                ah[1] = *(const uint32_t*)&sah[(r + 8) * KP + k0 + lc];
                ah[2] = *(const uint32_t*)&sah[r * KP + k0 + lc + 8];
                ah[3] = *(const uint32_t*)&sah[(r + 8) * KP + k0 + lc + 8];
#pragma unroll
                for (int nt = 0; nt < 2; nt++) {
                    mma16816h(c[mt][nt], ah, bh[nt]);
                    mma16816h(c[mt][nt], ah, bl[nt]);
                }
            }
        }

#pragma unroll
        for (int mt = 0; mt < 6; mt++) {
#pragma unroll
            for (int nt = 0; nt < 2; nt++) {
                const int ch0 = g * 96 + mt * 16 + lr;
                const long px = n0 + wpx + nt * 8 + lc;
                float b0 = __ldg(&bias[ch0]);
                float b1 = __ldg(&bias[ch0 + 8]);
                float2 v0 = { c[mt][nt][0] + b0, c[mt][nt][1] + b0 };
                float2 v1 = { c[mt][nt][2] + b1, c[mt][nt][3] + b1 };
                *(float2*)&Ob[(long)ch0 * HWPIX + px] = v0;
                *(float2*)&Ob[(long)(ch0 + 8) * HWPIX + px] = v1;
            }
        }
    }
}

// ---------------- K0: zero small accumulators ----------------
__global__ void zero_small() {
    int i = blockIdx.x * blockDim.x + threadIdx.x;
    if (i < B * HEADS * HC * HC) g_G[i] = 0.f;
    if (i < B * C) { g_qn[i] = 0.f; g_kn[i] = 0.f; }
}

// ---------------- K2: vectorized 3x3 depthwise conv (4 px/thread) ----------
// q,k -> packed bf16 hi/lo (+ norms); v -> packed fp16 hi/lo.
__global__ __launch_bounds__(256) void dwconv(
    const float* __restrict__ dw_w, const float* __restrict__ dw_b)
{
    const int tx = threadIdx.x;         // 0..63
    const int ty = threadIdx.y;         // 0..3
    const int ch = blockIdx.y;
    const int b  = blockIdx.z;
    const int col0 = tx * 4;
    const float* P = g_qkv + ((long)(b * C3 + ch)) * HWPIX;
    uint32_t*    O = (uint32_t*)(g_dw + ((long)(b * C3 + ch)) * HWPIX);

    float w[9];
#pragma unroll
    for (int t = 0; t < 9; t++) w[t] = __ldg(&dw_w[ch * 9 + t]);
    const float bias = __ldg(&dw_b[ch]);

    const int y0 = blockIdx.x * 32 + ty * 8;

    float A[6], Bw[6], Cw[6];
    auto loadrow = [&](int y, float* v) {
        if ((unsigned)y < 256u) {
            const float* row = P + y * WW + col0;
            float4 m = *(const float4*)row;
            v[0] = (col0 > 0)   ? __ldg(row - 1) : 0.f;
            v[1] = m.x; v[2] = m.y; v[3] = m.z; v[4] = m.w;
            v[5] = (col0 < 252) ? __ldg(row + 4) : 0.f;
        } else {
#pragma unroll
            for (int j = 0; j < 6; j++) v[j] = 0.f;
        }
    };
    loadrow(y0 - 1, A);
    loadrow(y0,     Bw);

    float ss = 0.f;
#pragma unroll
    for (int dy = 0; dy < 8; dy++) {
        loadrow(y0 + dy + 1, Cw);
        uint32_t pk[4];
#pragma unroll
        for (int j = 0; j < 4; j++) {
            float o = bias
                + w[0] * A[j]  + w[1] * A[j + 1]  + w[2] * A[j + 2]
                + w[3] * Bw[j] + w[4] * Bw[j + 1] + w[5] * Bw[j + 2]
                + w[6] * Cw[j] + w[7] * Cw[j + 1] + w[8] * Cw[j + 2];
            if (ch < 192) {
                ss += o * o;
                pk[j] = packbf(o, o - bf16val(o));
            } else {
                pk[j] = packh(o, o - h16val(o));
            }
        }
        *(uint4*)&O[(y0 + dy) * WW + col0] = *(uint4*)pk;
#pragma unroll
        for (int j = 0; j < 6; j++) { A[j] = Bw[j]; Bw[j] = Cw[j]; }
    }

    if (ch < 192) {
        const int tid = ty * 64 + tx;
#pragma unroll
        for (int o = 16; o; o >>= 1) ss += __shfl_down_sync(0xffffffffu, ss, o);
        __shared__ float red[8];
        if ((tid & 31) == 0) red[tid >> 5] = ss;
        __syncthreads();
        if (tid == 0) {
            float t = 0.f;
#pragma unroll
            for (int i = 0; i < 8; i++) t += red[i];
            float* dst = (ch < 96) ? &g_qn[b * C + ch] : &g_kn[b * C + ch - 96];
            atomicAdd(dst, t);
        }
    }
}

// ---------------- K3: Gram via mma.sync on packed bf16 {hi,lo} words --------
#define GPITCH 260
__global__ __launch_bounds__(256) void gram_mma()
{
    extern __shared__ uint32_t gsm[];
    uint32_t* qs = gsm;
    uint32_t* ks = gsm + 32 * GPITCH;
    float* red = (float*)gsm;

    const int chunk = blockIdx.x, h = blockIdx.y, b = blockIdx.z;
    const uint32_t* qg = (const uint32_t*)g_dw + ((long)(b * C3 + h * HC)) * HWPIX;
    const uint32_t* kg = (const uint32_t*)g_dw + ((long)(b * C3 + 96 + h * HC)) * HWPIX;
    const int tid = threadIdx.x, w = tid >> 5, l = tid & 31;
    const int lr = l >> 2, lq = l & 3;

    float c[2][4][4];
#pragma unroll
    for (int mt = 0; mt < 2; mt++)
#pragma unroll
        for (int nt = 0; nt < 4; nt++)
#pragma unroll
            for (int j = 0; j < 4; j++) c[mt][nt][j] = 0.f;

    const long base = (long)chunk * 1024;
    for (int s = 0; s < 4; s++) {
        const long n = base + s * 256;
        __syncthreads();
#pragma unroll
        for (int e = 0; e < 8; e++) {
            int i4 = e * 256 + tid;
            int ch = i4 >> 6, p4 = (i4 & 63) * 4;
            *(uint4*)&qs[ch * GPITCH + p4] = *(const uint4*)&qg[(long)ch * HWPIX + n + p4];
            *(uint4*)&ks[ch * GPITCH + p4] = *(const uint4*)&kg[(long)ch * HWPIX + n + p4];
        }
        __syncthreads();

        const int pxw = w * 32;
#pragma unroll
        for (int st = 0; st < 4; st++) {
            const int pxb = pxw + st * 8;
            uint32_t bh[4][2], bl[4][2];
#pragma unroll
            for (int nt = 0; nt < 4; nt++) {
                uint32_t r0 = ks[(nt * 8 + lr) * GPITCH + pxb + lq];
                uint32_t r1 = ks[(nt * 8 + lr) * GPITCH + pxb + 4 + lq];
                bh[nt][0] = prmt0(r0, 0x1010u); bl[nt][0] = prmt0(r0, 0x4432u);
                bh[nt][1] = prmt0(r1, 0x1010u); bl[nt][1] = prmt0(r1, 0x4432u);
            }
#pragma unroll
            for (int mt = 0; mt < 2; mt++) {
                uint32_t a[4];
                a[0] = qs[(mt * 16 + lr) * GPITCH + pxb + lq];
                a[1] = qs[(mt * 16 + 8 + lr) * GPITCH + pxb + lq];
                a[2] = qs[(mt * 16 + lr) * GPITCH + pxb + 4 + lq];
                a[3] = qs[(mt * 16 + 8 + lr) * GPITCH + pxb + 4 + lq];
#pragma unroll
                for (int nt = 0; nt < 4; nt++) {
                    mma16816bf(c[mt][nt], a, bh[nt]);
                    mma16816bf(c[mt][nt], a, bl[nt]);
                }
            }
        }
    }

    __syncthreads();
#pragma unroll
    for (int mt = 0; mt < 2; mt++)
#pragma unroll
        for (int nt = 0; nt < 4; nt++)
#pragma unroll
            for (int j = 0; j < 4; j++) {
                int row = mt * 16 + lr + ((j >> 1) << 3);
                int cl  = nt * 8 + lq * 2 + (j & 1);
                red[w * 1024 + row * 32 + cl] = c[mt][nt][j];
            }
    __syncthreads();
    float* Gp = g_G + (long)(b * HEADS + h) * HC * HC;
    for (int i = tid; i < 1024; i += 256) {
        float sum = 0.f;
#pragma unroll
        for (int ww = 0; ww < 8; ww++) sum += red[ww * 1024 + i];
        atomicAdd(&Gp[i], sum);
    }
}

// ---------------- K3b: softmax(G / (||q|| ||k||)) -> d_out tail ------------
__global__ void attn_softmax(float* __restrict__ out)
{
    const int blk = blockIdx.x;
    const int b = blk / 3, h = blk % 3;
    const int c = threadIdx.x;
    float nq = fmaxf(sqrtf(g_qn[b * C + h * HC + c]), 1e-12f);

    float v[32];
#pragma unroll
    for (int d = 0; d < 32; d++) {
        float nk = fmaxf(sqrtf(g_kn[b * C + h * HC + d]), 1e-12f);
        v[d] = g_G[(blk * HC + c) * HC + d] / (nq * nk);
    }
    float m = -1e30f;
#pragma unroll
    for (int d = 0; d < 32; d++) m = fmaxf(m, v[d]);
    float s = 0.f;
#pragma unroll
    for (int d = 0; d < 32; d++) { v[d] = expf(v[d] - m); s += v[d]; }
    float inv = 1.f / s;
    float* ap = out + OUT_ELEMS + (long)blk * (HC * HC) + c * HC;
#pragma unroll
    for (int d = 0; d < 32; d++) ap[d] = v[d] * inv;
}

// ---------------- K3c: M[b] = proj_w @ blockdiag(attn[b]) ----------------
__global__ void make_M(const float* __restrict__ proj_w, const float* __restrict__ out)
{
    const int b = blockIdx.x, tid = threadIdx.x;
    const float* attn = out + OUT_ELEMS;
#pragma unroll 4
    for (int e = 0; e < 36; e++) {
        int idx = e * 256 + tid;
        int o = idx / 96, g = idx % 96;
        int h = g >> 5, d = g & 31;
        const float* arow = attn + (long)(b * HEADS + h) * (HC * HC) + d;
        const float* prow = proj_w + o * 96 + h * HC;
        float s = 0.f;
#pragma unroll
        for (int cc = 0; cc < 32; cc++) s += prow[cc] * arow[cc * 32];
        g_M[(long)b * C * C + idx] = s;
    }
}

// ---------------- launch ----------------
extern "C" void kernel_launch(void* const* d_in, const int* in_sizes, int n_in,
                              void* d_out, int out_size)
{
    const float* x      = (const float*)d_in[0];
    const float* qkv_w  = (const float*)d_in[1];
    const float* qkv_b  = (const float*)d_in[2];
    const float* dw_w   = (const float*)d_in[3];
    const float* dw_b   = (const float*)d_in[4];
    const float* proj_w = (const float*)d_in[5];
    const float* proj_b = (const float*)d_in[6];
    float* out = (float*)d_out;

    const int smem_gemm = (2 * 128 * KP + 96 * KP) * 2;       // 73,216 B
    const int smem_gram = 2 * 32 * GPITCH * 4;                // 66,560 B
    cudaFuncSetAttribute(tmma_gemm<3>, cudaFuncAttributeMaxDynamicSharedMemorySize, smem_gemm);
    cudaFuncSetAttribute(tmma_gemm<1>, cudaFuncAttributeMaxDynamicSharedMemorySize, smem_gemm);
    cudaFuncSetAttribute(gram_mma,     cudaFuncAttributeMaxDynamicSharedMemorySize, smem_gram);

    zero_small<<<48, 256>>>();
    tmma_gemm<3><<<dim3(512, 1, B), 256, smem_gemm>>>(x, qkv_w, qkv_b, nullptr);
    dwconv<<<dim3(8, C3, B), dim3(64, 4)>>>(dw_w, dw_b);
    gram_mma<<<dim3(64, HEADS, B), 256, smem_gram>>>();
    attn_softmax<<<12, 32>>>(out);
    make_M<<<B, 256>>>(proj_w, out);
    tmma_gemm<1><<<dim3(512, 1, B), 256, smem_gemm>>>(nullptr, nullptr, proj_b, out);
}

// round 10
// speedup vs baseline: 1.2184x; 1.0836x over previous
#include <cuda_runtime.h>
#include <cuda_bf16.h>
#include <cuda_fp16.h>
#include <cstdint>

// Problem constants
#define B    4
#define C    96
#define C3   288
#define HH   256
#define WW   256
#define HWPIX 65536
#define HEADS 3
#define HC   32
#define OUT_ELEMS (B * C * HWPIX)

// ---------------- scratch (device globals) ----------------
__device__ uint16_t g_qkvh[(size_t)B * C3 * HWPIX];  // post 1x1 conv, fp16 single
__device__ float    g_dw [(size_t)B * 192 * HWPIX];  // post dw q,k; packed bf16 hi/lo
__device__ uint16_t g_vh [(size_t)B * C * HWPIX];    // post dw v, fp16 single
__device__ float g_G  [B * HEADS * HC * HC];
__device__ float g_qn [B * C];
__device__ float g_kn [B * C];
__device__ float g_M  [B * C * C];

// ---------------- helpers ----------------
__device__ __forceinline__ uint32_t packbf(float lo, float hi) {   // bf16x2
    uint32_t r;
    asm("cvt.rn.bf16x2.f32 %0, %1, %2;" : "=r"(r) : "f"(hi), "f"(lo));
    return r;
}
__device__ __forceinline__ uint32_t packh(float lo, float hi) {    // fp16x2
    uint32_t r;
    asm("cvt.rn.f16x2.f32 %0, %1, %2;" : "=r"(r) : "f"(hi), "f"(lo));
    return r;
}
__device__ __forceinline__ float bf16val(float v) {
    return __bfloat162float(__float2bfloat16(v));
}
__device__ __forceinline__ float h16val(float v) {
    return __half2float(__float2half_rn(v));
}
__device__ __forceinline__ uint32_t prmt0(uint32_t a, uint32_t sel) {
    uint32_t d, z = 0;
    asm("prmt.b32 %0, %1, %2, %3;" : "=r"(d) : "r"(a), "r"(z), "r"(sel));
    return d;
}

__device__ __forceinline__ void mma16816bf(float c[4], const uint32_t a[4],
                                           const uint32_t b[2]) {
    asm volatile(
        "mma.sync.aligned.m16n8k16.row.col.f32.bf16.bf16.f32 "
        "{%0,%1,%2,%3}, {%4,%5,%6,%7}, {%8,%9}, {%0,%1,%2,%3};"
        : "+f"(c[0]), "+f"(c[1]), "+f"(c[2]), "+f"(c[3])
        : "r"(a[0]), "r"(a[1]), "r"(a[2]), "r"(a[3]), "r"(b[0]), "r"(b[1]));
}
__device__ __forceinline__ void mma16816h(float c[4], const uint32_t a[4],
                                          const uint32_t b[2]) {
    asm volatile(
        "mma.sync.aligned.m16n8k16.row.col.f32.f16.f16.f32 "
        "{%0,%1,%2,%3}, {%4,%5,%6,%7}, {%8,%9}, {%0,%1,%2,%3};"
        : "+f"(c[0]), "+f"(c[1]), "+f"(c[2]), "+f"(c[3])
        : "r"(a[0]), "r"(a[1]), "r"(a[2]), "r"(a[3]), "r"(b[0]), "r"(b[1]));
}

// ========== tensor-core GEMM (fp16) ==========
// NG==3: x fp32 in -> B hi/lo (2 MMAs), out fp16 single to g_qkvh
// NG==1: v fp16 in -> B single (1 MMA),  out fp32 to d_out
#define KP 104

template<int NG>
__global__ __launch_bounds__(256) void tmma_gemm(
    const float* __restrict__ Xin, const float* __restrict__ Win,
    const float* __restrict__ bias, float* __restrict__ Oout)
{
    extern __shared__ __align__(16) uint16_t sm[];
    uint16_t* sbh = sm;                       // B hi [128][KP]
    uint16_t* sbl = sm + 128 * KP;            // B lo (NG==3 only)
    uint16_t* sah = sm + 2 * 128 * KP;        // A [96][KP] fp16

    const int tid  = threadIdx.x;
    const int warp = tid >> 5;
    const int l    = tid & 31;
    const int b    = blockIdx.z;
    const long n0  = (long)blockIdx.x * 128;

    const float* Wb;
    if constexpr (NG == 3) Wb = Win;
    else                   Wb = g_M + (long)b * C * C;

    // ---- B tile ----
    {
        const int px = tid & 127;
        const int kh = tid >> 7;
        if constexpr (NG == 3) {
            const float* Xb = Xin + (long)b * C * HWPIX;
            for (int k2 = kh; k2 < 48; k2 += 2) {
                const int k = k2 * 2;
                float v0 = Xb[(long)k * HWPIX + n0 + px];
                float v1 = Xb[(long)(k + 1) * HWPIX + n0 + px];
                float h0 = h16val(v0);
                float h1 = h16val(v1);
                *(uint32_t*)&sbh[px * KP + k] = packh(v0, v1);
                *(uint32_t*)&sbl[px * KP + k] = packh(v0 - h0, v1 - h1);
            }
        } else {
            const uint16_t* Xp = g_vh + (long)b * C * HWPIX;
            for (int k2 = kh; k2 < 48; k2 += 2) {
                const int k = k2 * 2;
                uint32_t w0 = Xp[(long)k * HWPIX + n0 + px];
                uint32_t w1 = Xp[(long)(k + 1) * HWPIX + n0 + px];
                *(uint32_t*)&sbh[px * KP + k] = w0 | (w1 << 16);
            }
        }
    }

    const int wpx = warp * 16;
    const int lr = l >> 2;
    const int lc = (l & 3) * 2;

    for (int g = 0; g < NG; g++) {
        __syncthreads();
        const float* Wg = Wb + (long)g * 96 * 96;
        for (int i = tid; i < 96 * 48; i += 256) {
            int m = i / 48, kp_ = (i - m * 48) * 2;
            float2 wv = *(const float2*)&Wg[m * 96 + kp_];
            *(uint32_t*)&sah[m * KP + kp_] = packh(wv.x, wv.y);
        }
        __syncthreads();

        float c[6][2][4];
#pragma unroll
        for (int mt = 0; mt < 6; mt++)
#pragma unroll
            for (int nt = 0; nt < 2; nt++)
#pragma unroll
                for (int j = 0; j < 4; j++) c[mt][nt][j] = 0.f;

#pragma unroll
        for (int s = 0; s < 6; s++) {
            const int k0 = s * 16;
            uint32_t bh[2][2], bl[2][2];
#pragma unroll
            for (int nt = 0; nt < 2; nt++) {
                const int n = wpx + nt * 8 + lr;
                bh[nt][0] = *(const uint32_t*)&sbh[n * KP + k0 + lc];
                bh[nt][1] = *(const uint32_t*)&sbh[n * KP + k0 + lc + 8];
                if constexpr (NG == 3) {
                    bl[nt][0] = *(const uint32_t*)&sbl[n * KP + k0 + lc];
                    bl[nt][1] = *(const uint32_t*)&sbl[n * KP + k0 + lc + 8];
                }
            }
#pragma unroll
            for (int mt = 0; mt < 6; mt++) {
                const int r = mt * 16 + lr;
                uint32_t ah[4];
                ah[0] = *(const uint32_t*)&sah[r * KP + k0 + lc];
                ah[1] = *(const uint32_t*)&sah[(r + 8) * KP + k0 + lc];
                ah[2] = *(const uint32_t*)&sah[r * KP + k0 + lc + 8];
                ah[3] = *(const uint32_t*)&sah[(r + 8) * KP + k0 + lc + 8];
#pragma unroll
                for (int nt = 0; nt < 2; nt++) {
                    mma16816h(c[mt][nt], ah, bh[nt]);
                    if constexpr (NG == 3) mma16816h(c[mt][nt], ah, bl[nt]);
                }
            }
        }

        // ---- epilogue ----
#pragma unroll
        for (int mt = 0; mt < 6; mt++) {
#pragma unroll
            for (int nt = 0; nt < 2; nt++) {
                const int ch0 = g * 96 + mt * 16 + lr;
                const long px = n0 + wpx + nt * 8 + lc;
                float b0 = __ldg(&bias[ch0]);
                float b1 = __ldg(&bias[ch0 + 8]);
                if constexpr (NG == 3) {
                    uint16_t* Oh = g_qkvh + (long)b * C3 * HWPIX;
                    *(uint32_t*)&Oh[(long)ch0 * HWPIX + px] =
                        packh(c[mt][nt][0] + b0, c[mt][nt][1] + b0);
                    *(uint32_t*)&Oh[(long)(ch0 + 8) * HWPIX + px] =
                        packh(c[mt][nt][2] + b1, c[mt][nt][3] + b1);
                } else {
                    float* Ob = Oout + (long)b * C * HWPIX;
                    float2 v0 = { c[mt][nt][0] + b0, c[mt][nt][1] + b0 };
                    float2 v1 = { c[mt][nt][2] + b1, c[mt][nt][3] + b1 };
                    *(float2*)&Ob[(long)ch0 * HWPIX + px] = v0;
                    *(float2*)&Ob[(long)(ch0 + 8) * HWPIX + px] = v1;
                }
            }
        }
    }
}

// ---------------- K0: zero small accumulators ----------------
__global__ void zero_small() {
    int i = blockIdx.x * blockDim.x + threadIdx.x;
    if (i < B * HEADS * HC * HC) g_G[i] = 0.f;
    if (i < B * C) { g_qn[i] = 0.f; g_kn[i] = 0.f; }
}

// ---------------- K2: depthwise conv on fp16 input (4 px/thread) ----------
// q,k -> packed bf16 hi/lo (+ norms) into g_dw; v -> fp16 single into g_vh.
__global__ __launch_bounds__(256) void dwconv(
    const float* __restrict__ dw_w, const float* __restrict__ dw_b)
{
    const int tx = threadIdx.x;         // 0..63
    const int ty = threadIdx.y;         // 0..3
    const int ch = blockIdx.y;
    const int b  = blockIdx.z;
    const int col0 = tx * 4;
    const __half* P = (const __half*)(g_qkvh + ((long)(b * C3 + ch)) * HWPIX);

    float w[9];
#pragma unroll
    for (int t = 0; t < 9; t++) w[t] = __ldg(&dw_w[ch * 9 + t]);
    const float bias = __ldg(&dw_b[ch]);

    const int y0 = blockIdx.x * 32 + ty * 8;

    float A[6], Bw[6], Cw[6];
    auto loadrow = [&](int y, float* v) {
        if ((unsigned)y < 256u) {
            const __half* row = P + y * WW + col0;
            uint2 m = *(const uint2*)row;
            __half2 p0 = *(__half2*)&m.x;
            __half2 p1 = *(__half2*)&m.y;
            v[0] = (col0 > 0)   ? __half2float(__ldg(row - 1)) : 0.f;
            v[1] = __low2float(p0);  v[2] = __high2float(p0);
            v[3] = __low2float(p1);  v[4] = __high2float(p1);
            v[5] = (col0 < 252) ? __half2float(__ldg(row + 4)) : 0.f;
        } else {
#pragma unroll
            for (int j = 0; j < 6; j++) v[j] = 0.f;
        }
    };
    loadrow(y0 - 1, A);
    loadrow(y0,     Bw);

    float ss = 0.f;
#pragma unroll
    for (int dy = 0; dy < 8; dy++) {
        loadrow(y0 + dy + 1, Cw);
        if (ch < 192) {
            uint32_t* O = (uint32_t*)(g_dw + ((long)(b * 192 + ch)) * HWPIX);
            uint32_t pk[4];
#pragma unroll
            for (int j = 0; j < 4; j++) {
                float o = bias
                    + w[0] * A[j]  + w[1] * A[j + 1]  + w[2] * A[j + 2]
                    + w[3] * Bw[j] + w[4] * Bw[j + 1] + w[5] * Bw[j + 2]
                    + w[6] * Cw[j] + w[7] * Cw[j + 1] + w[8] * Cw[j + 2];
                ss += o * o;
                pk[j] = packbf(o, o - bf16val(o));
            }
            *(uint4*)&O[(y0 + dy) * WW + col0] = *(uint4*)pk;
        } else {
            uint16_t* O = g_vh + ((long)(b * C + (ch - 192))) * HWPIX;
            float o0[4];
#pragma unroll
            for (int j = 0; j < 4; j++) {
                o0[j] = bias
                    + w[0] * A[j]  + w[1] * A[j + 1]  + w[2] * A[j + 2]
                    + w[3] * Bw[j] + w[4] * Bw[j + 1] + w[5] * Bw[j + 2]
                    + w[6] * Cw[j] + w[7] * Cw[j + 1] + w[8] * Cw[j + 2];
            }
            uint2 st;
            st.x = packh(o0[0], o0[1]);
            st.y = packh(o0[2], o0[3]);
            *(uint2*)&O[(y0 + dy) * WW + col0] = st;
        }
#pragma unroll
        for (int j = 0; j < 6; j++) { A[j] = Bw[j]; Bw[j] = Cw[j]; }
    }

    if (ch < 192) {
        const int tid = ty * 64 + tx;
#pragma unroll
        for (int o = 16; o; o >>= 1) ss += __shfl_down_sync(0xffffffffu, ss, o);
        __shared__ float red[8];
        if ((tid & 31) == 0) red[tid >> 5] = ss;
        __syncthreads();
        if (tid == 0) {
            float t = 0.f;
#pragma unroll
            for (int i = 0; i < 8; i++) t += red[i];
            float* dst = (ch < 96) ? &g_qn[b * C + ch] : &g_kn[b * C + ch - 96];
            atomicAdd(dst, t);
        }
    }
}

// ---------------- K3: Gram via mma.sync on packed bf16 {hi,lo} words --------
#define GPITCH 260
__global__ __launch_bounds__(256) void gram_mma()
{
    extern __shared__ uint32_t gsm[];
    uint32_t* qs = gsm;
    uint32_t* ks = gsm + 32 * GPITCH;
    float* red = (float*)gsm;

    const int chunk = blockIdx.x, h = blockIdx.y, b = blockIdx.z;
    const uint32_t* qg = (const uint32_t*)g_dw + ((long)(b * 192 + h * HC)) * HWPIX;
    const uint32_t* kg = (const uint32_t*)g_dw + ((long)(b * 192 + 96 + h * HC)) * HWPIX;
    const int tid = threadIdx.x, w = tid >> 5, l = tid & 31;
    const int lr = l >> 2, lq = l & 3;

    float c[2][4][4];
#pragma unroll
    for (int mt = 0; mt < 2; mt++)
#pragma unroll
        for (int nt = 0; nt < 4; nt++)
#pragma unroll
            for (int j = 0; j < 4; j++) c[mt][nt][j] = 0.f;

    const long base = (long)chunk * 1024;
    for (int s = 0; s < 4; s++) {
        const long n = base + s * 256;
        __syncthreads();
#pragma unroll
        for (int e = 0; e < 8; e++) {
            int i4 = e * 256 + tid;
            int ch = i4 >> 6, p4 = (i4 & 63) * 4;
            *(uint4*)&qs[ch * GPITCH + p4] = *(const uint4*)&qg[(long)ch * HWPIX + n + p4];
            *(uint4*)&ks[ch * GPITCH + p4] = *(const uint4*)&kg[(long)ch * HWPIX + n + p4];
        }
        __syncthreads();

        const int pxw = w * 32;
#pragma unroll
        for (int st = 0; st < 4; st++) {
            const int pxb = pxw + st * 8;
            uint32_t bh[4][2], bl[4][2];
#pragma unroll
            for (int nt = 0; nt < 4; nt++) {
                uint32_t r0 = ks[(nt * 8 + lr) * GPITCH + pxb + lq];
                uint32_t r1 = ks[(nt * 8 + lr) * GPITCH + pxb + 4 + lq];
                bh[nt][0] = prmt0(r0, 0x1010u); bl[nt][0] = prmt0(r0, 0x4432u);
                bh[nt][1] = prmt0(r1, 0x1010u); bl[nt][1] = prmt0(r1, 0x4432u);
            }
#pragma unroll
            for (int mt = 0; mt < 2; mt++) {
                uint32_t a[4];
                a[0] = qs[(mt * 16 + lr) * GPITCH + pxb + lq];
                a[1] = qs[(mt * 16 + 8 + lr) * GPITCH + pxb + lq];
                a[2] = qs[(mt * 16 + lr) * GPITCH + pxb + 4 + lq];
                a[3] = qs[(mt * 16 + 8 + lr) * GPITCH + pxb + 4 + lq];
#pragma unroll
                for (int nt = 0; nt < 4; nt++) {
                    mma16816bf(c[mt][nt], a, bh[nt]);
                    mma16816bf(c[mt][nt], a, bl[nt]);
                }
            }
        }
    }

    __syncthreads();
#pragma unroll
    for (int mt = 0; mt < 2; mt++)
#pragma unroll
        for (int nt = 0; nt < 4; nt++)
#pragma unroll
            for (int j = 0; j < 4; j++) {
                int row = mt * 16 + lr + ((j >> 1) << 3);
                int cl  = nt * 8 + lq * 2 + (j & 1);
                red[w * 1024 + row * 32 + cl] = c[mt][nt][j];
            }
    __syncthreads();
    float* Gp = g_G + (long)(b * HEADS + h) * HC * HC;
    for (int i = tid; i < 1024; i += 256) {
        float sum = 0.f;
#pragma unroll
        for (int ww = 0; ww < 8; ww++) sum += red[ww * 1024 + i];
        atomicAdd(&Gp[i], sum);
    }
}

// ---------------- K3b: softmax(G / (||q|| ||k||)) -> d_out tail ------------
__global__ void attn_softmax(float* __restrict__ out)
{
    const int blk = blockIdx.x;
    const int b = blk / 3, h = blk % 3;
    const int c = threadIdx.x;
    float nq = fmaxf(sqrtf(g_qn[b * C + h * HC + c]), 1e-12f);

    float v[32];
#pragma unroll
    for (int d = 0; d < 32; d++) {
        float nk = fmaxf(sqrtf(g_kn[b * C + h * HC + d]), 1e-12f);
        v[d] = g_G[(blk * HC + c) * HC + d] / (nq * nk);
    }
    float m = -1e30f;
#pragma unroll
    for (int d = 0; d < 32; d++) m = fmaxf(m, v[d]);
    float s = 0.f;
#pragma unroll
    for (int d = 0; d < 32; d++) { v[d] = expf(v[d] - m); s += v[d]; }
    float inv = 1.f / s;
    float* ap = out + OUT_ELEMS + (long)blk * (HC * HC) + c * HC;
#pragma unroll
    for (int d = 0; d < 32; d++) ap[d] = v[d] * inv;
}

// ---------------- K3c: M[b] = proj_w @ blockdiag(attn[b]) ----------------
__global__ void make_M(const float* __restrict__ proj_w, const float* __restrict__ out)
{
    const int b = blockIdx.x, tid = threadIdx.x;
    const float* attn = out + OUT_ELEMS;
#pragma unroll 4
    for (int e = 0; e < 36; e++) {
        int idx = e * 256 + tid;
        int o = idx / 96, g = idx % 96;
        int h = g >> 5, d = g & 31;
        const float* arow = attn + (long)(b * HEADS + h) * (HC * HC) + d;
        const float* prow = proj_w + o * 96 + h * HC;
        float s = 0.f;
#pragma unroll
        for (int cc = 0; cc < 32; cc++) s += prow[cc] * arow[cc * 32];
        g_M[(long)b * C * C + idx] = s;
    }
}

// ---------------- launch ----------------
extern "C" void kernel_launch(void* const* d_in, const int* in_sizes, int n_in,
                              void* d_out, int out_size)
{
    const float* x      = (const float*)d_in[0];
    const float* qkv_w  = (const float*)d_in[1];
    const float* qkv_b  = (const float*)d_in[2];
    const float* dw_w   = (const float*)d_in[3];
    const float* dw_b   = (const float*)d_in[4];
    const float* proj_w = (const float*)d_in[5];
    const float* proj_b = (const float*)d_in[6];
    float* out = (float*)d_out;

    const int smem_gemm = (2 * 128 * KP + 96 * KP) * 2;       // 73,216 B
    const int smem_gram = 2 * 32 * GPITCH * 4;                // 66,560 B
    cudaFuncSetAttribute(tmma_gemm<3>, cudaFuncAttributeMaxDynamicSharedMemorySize, smem_gemm);
    cudaFuncSetAttribute(tmma_gemm<1>, cudaFuncAttributeMaxDynamicSharedMemorySize, smem_gemm);
    cudaFuncSetAttribute(gram_mma,     cudaFuncAttributeMaxDynamicSharedMemorySize, smem_gram);

    zero_small<<<48, 256>>>();
    tmma_gemm<3><<<dim3(512, 1, B), 256, smem_gemm>>>(x, qkv_w, qkv_b, nullptr);
    dwconv<<<dim3(8, C3, B), dim3(64, 4)>>>(dw_w, dw_b);
    gram_mma<<<dim3(64, HEADS, B), 256, smem_gram>>>();
    attn_softmax<<<12, 32>>>(out);
    make_M<<<B, 256>>>(proj_w, out);
    tmma_gemm<1><<<dim3(512, 1, B), 256, smem_gemm>>>(nullptr, nullptr, proj_b, out);
}

// round 11
// speedup vs baseline: 1.5893x; 1.3045x over previous
#include <cuda_runtime.h>
#include <cuda_bf16.h>
#include <cuda_fp16.h>
#include <cstdint>

// Problem constants
#define B    4
#define C    96
#define C3   288
#define HH   256
#define WW   256
#define HWPIX 65536
#define HEADS 3
#define HC   32
#define OUT_ELEMS (B * C * HWPIX)

// ---------------- scratch (device globals) ----------------
__device__ uint16_t g_qkvh[(size_t)B * C3 * HWPIX];  // post 1x1 conv, fp16 single
__device__ uint16_t g_qk [(size_t)B * 192 * HWPIX];  // post dw q,k; fp16 single
__device__ uint16_t g_vh [(size_t)B * C * HWPIX];    // post dw v, fp16 single
__device__ float g_G  [B * HEADS * HC * HC];
__device__ float g_qn [B * C];
__device__ float g_kn [B * C];
__device__ float g_M  [B * C * C];

// ---------------- helpers ----------------
__device__ __forceinline__ uint32_t packh(float lo, float hi) {    // fp16x2
    uint32_t r;
    asm("cvt.rn.f16x2.f32 %0, %1, %2;" : "=r"(r) : "f"(hi), "f"(lo));
    return r;
}

__device__ __forceinline__ void mma16816h(float c[4], const uint32_t a[4],
                                          const uint32_t b[2]) {
    asm volatile(
        "mma.sync.aligned.m16n8k16.row.col.f32.f16.f16.f32 "
        "{%0,%1,%2,%3}, {%4,%5,%6,%7}, {%8,%9}, {%0,%1,%2,%3};"
        : "+f"(c[0]), "+f"(c[1]), "+f"(c[2]), "+f"(c[3])
        : "r"(a[0]), "r"(a[1]), "r"(a[2]), "r"(a[3]), "r"(b[0]), "r"(b[1]));
}

// ========== tensor-core GEMM (fp16 single-product) ==========
// NG==3: x fp32 in -> fp16, out fp16 single to g_qkvh
// NG==1: v fp16 in, out fp32 to d_out
#define KP 104

template<int NG>
__global__ __launch_bounds__(256) void tmma_gemm(
    const float* __restrict__ Xin, const float* __restrict__ Win,
    const float* __restrict__ bias, float* __restrict__ Oout)
{
    extern __shared__ __align__(16) uint16_t sm[];
    uint16_t* sbh = sm;                       // B [128][KP] fp16
    uint16_t* sah = sm + 128 * KP;            // A [96][KP] fp16

    const int tid  = threadIdx.x;
    const int warp = tid >> 5;
    const int l    = tid & 31;
    const int b    = blockIdx.z;
    const long n0  = (long)blockIdx.x * 128;

    const float* Wb;
    if constexpr (NG == 3) Wb = Win;
    else                   Wb = g_M + (long)b * C * C;

    // ---- B tile: X[k][px] -> smem [px][k] fp16 ----
    {
        const int px = tid & 127;
        const int kh = tid >> 7;
        if constexpr (NG == 3) {
            const float* Xb = Xin + (long)b * C * HWPIX;
            for (int k2 = kh; k2 < 48; k2 += 2) {
                const int k = k2 * 2;
                float v0 = Xb[(long)k * HWPIX + n0 + px];
                float v1 = Xb[(long)(k + 1) * HWPIX + n0 + px];
                *(uint32_t*)&sbh[px * KP + k] = packh(v0, v1);
            }
        } else {
            const uint16_t* Xp = g_vh + (long)b * C * HWPIX;
            for (int k2 = kh; k2 < 48; k2 += 2) {
                const int k = k2 * 2;
                uint32_t w0 = Xp[(long)k * HWPIX + n0 + px];
                uint32_t w1 = Xp[(long)(k + 1) * HWPIX + n0 + px];
                *(uint32_t*)&sbh[px * KP + k] = w0 | (w1 << 16);
            }
        }
    }

    const int wpx = warp * 16;
    const int lr = l >> 2;
    const int lc = (l & 3) * 2;

    for (int g = 0; g < NG; g++) {
        __syncthreads();
        const float* Wg = Wb + (long)g * 96 * 96;
        for (int i = tid; i < 96 * 48; i += 256) {
            int m = i / 48, kp_ = (i - m * 48) * 2;
            float2 wv = *(const float2*)&Wg[m * 96 + kp_];
            *(uint32_t*)&sah[m * KP + kp_] = packh(wv.x, wv.y);
        }
        __syncthreads();

        float c[6][2][4];
#pragma unroll
        for (int mt = 0; mt < 6; mt++)
#pragma unroll
            for (int nt = 0; nt < 2; nt++)
#pragma unroll
                for (int j = 0; j < 4; j++) c[mt][nt][j] = 0.f;

#pragma unroll
        for (int s = 0; s < 6; s++) {
            const int k0 = s * 16;
            uint32_t bh[2][2];
#pragma unroll
            for (int nt = 0; nt < 2; nt++) {
                const int n = wpx + nt * 8 + lr;
                bh[nt][0] = *(const uint32_t*)&sbh[n * KP + k0 + lc];
                bh[nt][1] = *(const uint32_t*)&sbh[n * KP + k0 + lc + 8];
            }
#pragma unroll
            for (int mt = 0; mt < 6; mt++) {
                const int r = mt * 16 + lr;
                uint32_t ah[4];
                ah[0] = *(const uint32_t*)&sah[r * KP + k0 + lc];
                ah[1] = *(const uint32_t*)&sah[(r + 8) * KP + k0 + lc];
                ah[2] = *(const uint32_t*)&sah[r * KP + k0 + lc + 8];
                ah[3] = *(const uint32_t*)&sah[(r + 8) * KP + k0 + lc + 8];
#pragma unroll
                for (int nt = 0; nt < 2; nt++)
                    mma16816h(c[mt][nt], ah, bh[nt]);
            }
        }

        // ---- epilogue ----
#pragma unroll
        for (int mt = 0; mt < 6; mt++) {
#pragma unroll
            for (int nt = 0; nt < 2; nt++) {
                const int ch0 = g * 96 + mt * 16 + lr;
                const long px = n0 + wpx + nt * 8 + lc;
                float b0 = __ldg(&bias[ch0]);
                float b1 = __ldg(&bias[ch0 + 8]);
                if constexpr (NG == 3) {
                    uint16_t* Oh = g_qkvh + (long)b * C3 * HWPIX;
                    *(uint32_t*)&Oh[(long)ch0 * HWPIX + px] =
                        packh(c[mt][nt][0] + b0, c[mt][nt][1] + b0);
                    *(uint32_t*)&Oh[(long)(ch0 + 8) * HWPIX + px] =
                        packh(c[mt][nt][2] + b1, c[mt][nt][3] + b1);
                } else {
                    float* Ob = Oout + (long)b * C * HWPIX;
                    float2 v0 = { c[mt][nt][0] + b0, c[mt][nt][1] + b0 };
                    float2 v1 = { c[mt][nt][2] + b1, c[mt][nt][3] + b1 };
                    *(float2*)&Ob[(long)ch0 * HWPIX + px] = v0;
                    *(float2*)&Ob[(long)(ch0 + 8) * HWPIX + px] = v1;
                }
            }
        }
    }
}

// ---------------- K0: zero small accumulators ----------------
__global__ void zero_small() {
    int i = blockIdx.x * blockDim.x + threadIdx.x;
    if (i < B * HEADS * HC * HC) g_G[i] = 0.f;
    if (i < B * C) { g_qn[i] = 0.f; g_kn[i] = 0.f; }
}

// ---------------- K2: depthwise conv on fp16 input (4 px/thread) ----------
// q,k -> fp16 single into g_qk (+ norms); v -> fp16 single into g_vh.
__global__ __launch_bounds__(256) void dwconv(
    const float* __restrict__ dw_w, const float* __restrict__ dw_b)
{
    const int tx = threadIdx.x;         // 0..63
    const int ty = threadIdx.y;         // 0..3
    const int ch = blockIdx.y;
    const int b  = blockIdx.z;
    const int col0 = tx * 4;
    const __half* P = (const __half*)(g_qkvh + ((long)(b * C3 + ch)) * HWPIX);

    float w[9];
#pragma unroll
    for (int t = 0; t < 9; t++) w[t] = __ldg(&dw_w[ch * 9 + t]);
    const float bias = __ldg(&dw_b[ch]);

    const int y0 = blockIdx.x * 32 + ty * 8;

    float A[6], Bw[6], Cw[6];
    auto loadrow = [&](int y, float* v) {
        if ((unsigned)y < 256u) {
            const __half* row = P + y * WW + col0;
            uint2 m = *(const uint2*)row;
            __half2 p0 = *(__half2*)&m.x;
            __half2 p1 = *(__half2*)&m.y;
            v[0] = (col0 > 0)   ? __half2float(__ldg(row - 1)) : 0.f;
            v[1] = __low2float(p0);  v[2] = __high2float(p0);
            v[3] = __low2float(p1);  v[4] = __high2float(p1);
            v[5] = (col0 < 252) ? __half2float(__ldg(row + 4)) : 0.f;
        } else {
#pragma unroll
            for (int j = 0; j < 6; j++) v[j] = 0.f;
        }
    };
    loadrow(y0 - 1, A);
    loadrow(y0,     Bw);

    uint16_t* O = (ch < 192) ? (g_qk + ((long)(b * 192 + ch)) * HWPIX)
                             : (g_vh + ((long)(b * C + (ch - 192))) * HWPIX);

    float ss = 0.f;
#pragma unroll
    for (int dy = 0; dy < 8; dy++) {
        loadrow(y0 + dy + 1, Cw);
        float o0[4];
#pragma unroll
        for (int j = 0; j < 4; j++) {
            o0[j] = bias
                + w[0] * A[j]  + w[1] * A[j + 1]  + w[2] * A[j + 2]
                + w[3] * Bw[j] + w[4] * Bw[j + 1] + w[5] * Bw[j + 2]
                + w[6] * Cw[j] + w[7] * Cw[j + 1] + w[8] * Cw[j + 2];
            ss += o0[j] * o0[j];
        }
        uint2 st;
        st.x = packh(o0[0], o0[1]);
        st.y = packh(o0[2], o0[3]);
        *(uint2*)&O[(y0 + dy) * WW + col0] = st;
#pragma unroll
        for (int j = 0; j < 6; j++) { A[j] = Bw[j]; Bw[j] = Cw[j]; }
    }

    if (ch < 192) {
        const int tid = ty * 64 + tx;
#pragma unroll
        for (int o = 16; o; o >>= 1) ss += __shfl_down_sync(0xffffffffu, ss, o);
        __shared__ float red[8];
        if ((tid & 31) == 0) red[tid >> 5] = ss;
        __syncthreads();
        if (tid == 0) {
            float t = 0.f;
#pragma unroll
            for (int i = 0; i < 8; i++) t += red[i];
            float* dst = (ch < 96) ? &g_qn[b * C + ch] : &g_kn[b * C + ch - 96];
            atomicAdd(dst, t);
        }
    }
}

// ---------------- K3: Gram via fp16 mma.sync (single product) ---------------
// grid (64, 3, 4), block 256. Chunk = 1024 px, 4 slices of 256 px.
// smem: qs,ks [32 ch][256 px] fp16, pitch 132 uint32 words. ~34 KB.
#define GP32 132
__global__ __launch_bounds__(256) void gram_mma()
{
    extern __shared__ uint32_t gsm[];
    uint32_t* qs = gsm;
    uint32_t* ks = gsm + 32 * GP32;
    float* red = (float*)gsm;          // reuse: [8][1024] floats = 32 KB

    const int chunk = blockIdx.x, h = blockIdx.y, b = blockIdx.z;
    const uint16_t* qg = g_qk + ((long)(b * 192 + h * HC)) * HWPIX;
    const uint16_t* kg = g_qk + ((long)(b * 192 + 96 + h * HC)) * HWPIX;
    const int tid = threadIdx.x, w = tid >> 5, l = tid & 31;
    const int lr = l >> 2, lq = l & 3;

    float c[2][4][4];
#pragma unroll
    for (int mt = 0; mt < 2; mt++)
#pragma unroll
        for (int nt = 0; nt < 4; nt++)
#pragma unroll
            for (int j = 0; j < 4; j++) c[mt][nt][j] = 0.f;

    const long base = (long)chunk * 1024;
    for (int s = 0; s < 4; s++) {
        const long n = base + s * 256;
        __syncthreads();
#pragma unroll
        for (int e = 0; e < 4; e++) {
            int i4 = e * 256 + tid;          // 0..1023
            int ch = i4 >> 5, u = i4 & 31;   // u: uint4 index (8 px)
            *(uint4*)&qs[ch * GP32 + u * 4] = *(const uint4*)&qg[(long)ch * HWPIX + n + u * 8];
            *(uint4*)&ks[ch * GP32 + u * 4] = *(const uint4*)&kg[(long)ch * HWPIX + n + u * 8];
        }
        __syncthreads();

        const int pxw = w * 32;              // warp's 32-px span (K dim)
#pragma unroll
        for (int st = 0; st < 2; st++) {
            const int wb = (pxw + st * 16) >> 1;   // word base
            uint32_t bh[4][2];
#pragma unroll
            for (int nt = 0; nt < 4; nt++) {
                bh[nt][0] = ks[(nt * 8 + lr) * GP32 + wb + lq];
                bh[nt][1] = ks[(nt * 8 + lr) * GP32 + wb + 4 + lq];
            }
#pragma unroll
            for (int mt = 0; mt < 2; mt++) {
                uint32_t a[4];
                a[0] = qs[(mt * 16 + lr) * GP32 + wb + lq];
                a[1] = qs[(mt * 16 + 8 + lr) * GP32 + wb + lq];
                a[2] = qs[(mt * 16 + lr) * GP32 + wb + 4 + lq];
                a[3] = qs[(mt * 16 + 8 + lr) * GP32 + wb + 4 + lq];
#pragma unroll
                for (int nt = 0; nt < 4; nt++)
                    mma16816h(c[mt][nt], a, bh[nt]);
            }
        }
    }

    __syncthreads();
#pragma unroll
    for (int mt = 0; mt < 2; mt++)
#pragma unroll
        for (int nt = 0; nt < 4; nt++)
#pragma unroll
            for (int j = 0; j < 4; j++) {
                int row = mt * 16 + lr + ((j >> 1) << 3);
                int cl  = nt * 8 + lq * 2 + (j & 1);
                red[w * 1024 + row * 32 + cl] = c[mt][nt][j];
            }
    __syncthreads();
    float* Gp = g_G + (long)(b * HEADS + h) * HC * HC;
    for (int i = tid; i < 1024; i += 256) {
        float sum = 0.f;
#pragma unroll
        for (int ww = 0; ww < 8; ww++) sum += red[ww * 1024 + i];
        atomicAdd(&Gp[i], sum);
    }
}

// ---------------- K3b: softmax(G / (||q|| ||k||)) -> d_out tail ------------
__global__ void attn_softmax(float* __restrict__ out)
{
    const int blk = blockIdx.x;
    const int b = blk / 3, h = blk % 3;
    const int c = threadIdx.x;
    float nq = fmaxf(sqrtf(g_qn[b * C + h * HC + c]), 1e-12f);

    float v[32];
#pragma unroll
    for (int d = 0; d < 32; d++) {
        float nk = fmaxf(sqrtf(g_kn[b * C + h * HC + d]), 1e-12f);
        v[d] = g_G[(blk * HC + c) * HC + d] / (nq * nk);
    }
    float m = -1e30f;
#pragma unroll
    for (int d = 0; d < 32; d++) m = fmaxf(m, v[d]);
    float s = 0.f;
#pragma unroll
    for (int d = 0; d < 32; d++) { v[d] = expf(v[d] - m); s += v[d]; }
    float inv = 1.f / s;
    float* ap = out + OUT_ELEMS + (long)blk * (HC * HC) + c * HC;
#pragma unroll
    for (int d = 0; d < 32; d++) ap[d] = v[d] * inv;
}

// ---------------- K3c: M[b] = proj_w @ blockdiag(attn[b]) ----------------
__global__ void make_M(const float* __restrict__ proj_w, const float* __restrict__ out)
{
    const int b = blockIdx.x, tid = threadIdx.x;
    const float* attn = out + OUT_ELEMS;
#pragma unroll 4
    for (int e = 0; e < 36; e++) {
        int idx = e * 256 + tid;
        int o = idx / 96, g = idx % 96;
        int h = g >> 5, d = g & 31;
        const float* arow = attn + (long)(b * HEADS + h) * (HC * HC) + d;
        const float* prow = proj_w + o * 96 + h * HC;
        float s = 0.f;
#pragma unroll
        for (int cc = 0; cc < 32; cc++) s += prow[cc] * arow[cc * 32];
        g_M[(long)b * C * C + idx] = s;
    }
}

// ---------------- launch ----------------
extern "C" void kernel_launch(void* const* d_in, const int* in_sizes, int n_in,
                              void* d_out, int out_size)
{
    const float* x      = (const float*)d_in[0];
    const float* qkv_w  = (const float*)d_in[1];
    const float* qkv_b  = (const float*)d_in[2];
    const float* dw_w   = (const float*)d_in[3];
    const float* dw_b   = (const float*)d_in[4];
    const float* proj_w = (const float*)d_in[5];
    const float* proj_b = (const float*)d_in[6];
    float* out = (float*)d_out;

    const int smem_gemm = (128 * KP + 96 * KP) * 2;           // 46,592 B
    const int smem_gram = 2 * 32 * GP32 * 4;                  // 33,792 B
    cudaFuncSetAttribute(tmma_gemm<3>, cudaFuncAttributeMaxDynamicSharedMemorySize, smem_gemm);
    cudaFuncSetAttribute(tmma_gemm<1>, cudaFuncAttributeMaxDynamicSharedMemorySize, smem_gemm);
    cudaFuncSetAttribute(gram_mma,     cudaFuncAttributeMaxDynamicSharedMemorySize, smem_gram);

    zero_small<<<48, 256>>>();
    tmma_gemm<3><<<dim3(512, 1, B), 256, smem_gemm>>>(x, qkv_w, qkv_b, nullptr);
    dwconv<<<dim3(8, C3, B), dim3(64, 4)>>>(dw_w, dw_b);
    gram_mma<<<dim3(64, HEADS, B), 256, smem_gram>>>();
    attn_softmax<<<12, 32>>>(out);
    make_M<<<B, 256>>>(proj_w, out);
    tmma_gemm<1><<<dim3(512, 1, B), 256, smem_gemm>>>(nullptr, nullptr, proj_b, out);
}